// round 9
// baseline (speedup 1.0000x reference)
#include <cuda_runtime.h>
#include <stdint.h>

// ---------------------------------------------------------------------------
// W4A8 per-group GEMM via legacy **bf16 HMMA** (tcgen05 compiler-blocked;
// legacy IMMA measured at a hard ~47.8us pipe wall across rounds 1-8).
// Exactness: x in [-128,127], w = q*s2+z in [-105,105] -> both exact in bf16
// (<=8 significant bits); products exact in fp32; fp32 accumulation matches
// the fp32 reference einsum (~1e-7 rel err).
//   acc[m,o] = sum_k bf16(x) * bf16(w)   (f32 acc, mma.m16n8k16)
//   out[m,o] = acc * isc[m] * s1[o] + bias[o]
// Structure = round 8: NT=32 (448 CTAs), 256 thr, register-prefetched W,
// double-buffered smem tiles, ldmatrix fragment loads, 1 sync/group.
// ---------------------------------------------------------------------------

#define M_DIM 64
#define K_DIM 4096
#define N_DIM 14336
#define G_DIM 32
#define GS    128            // K per group
#define NT    32             // output channels per CTA -> 448 CTAs
#define BROW  272            // bytes per tile row (256 data + 16 pad; 68 words,
                             // 68 mod 32 = 4 -> ldmatrix phases conflict-free)
#define THREADS 256
#define TILE_A (M_DIM * BROW)            // 17408 B (64 x 128 bf16)
#define TILE_B (NT * BROW)               // 8704 B  (32 x 128 bf16)
#define SMEM_TOTAL (2 * (TILE_A + TILE_B))  // 52224 B

__device__ __forceinline__ unsigned smem_u32(const void* p) {
    unsigned a;
    asm("{ .reg .u64 t; cvta.to.shared.u64 t, %1; cvt.u32.u64 %0, t; }" : "=r"(a) : "l"(p));
    return a;
}
// pack two fp32 -> bf16x2 word: hi = fhi, lo = flo
__device__ __forceinline__ unsigned bf16x2(float fhi, float flo) {
    unsigned r;
    asm("cvt.rn.bf16x2.f32 %0, %1, %2;" : "=r"(r) : "f"(fhi), "f"(flo));
    return r;
}

// bf16-packed activations [M][K] (512 KB static scratch), as 32-bit words
__device__ __align__(16) unsigned int g_x_bf16[M_DIM * K_DIM / 2];

// ---- pass 0: pack x int32 -> bf16 --------------------------------------------
__global__ void pack_x_kernel(const int* __restrict__ x) {
    int idx = blockIdx.x * blockDim.x + threadIdx.x;   // one int4 (4 values)
    if (idx >= M_DIM * K_DIM / 4) return;
    const int4 v = reinterpret_cast<const int4*>(x)[idx];
    uint2 w;
    w.x = bf16x2((float)v.y, (float)v.x);   // lo word: k even first
    w.y = bf16x2((float)v.w, (float)v.z);
    reinterpret_cast<uint2*>(g_x_bf16)[idx] = w;
}

// ---- main GEMM ---------------------------------------------------------------
__global__ __launch_bounds__(THREADS, 3)
void w4a8_gemm_kernel(const int*   __restrict__ qw,    // [N,K] int32 (0..15)
                      const int*   __restrict__ s2s,   // [G,N]
                      const int*   __restrict__ s2z,   // [G,N]
                      const float* __restrict__ isc,   // [M]
                      const float* __restrict__ s1,    // [N]
                      const float* __restrict__ bias,  // [N]
                      float*       __restrict__ out)   // [M,N]
{
    extern __shared__ __align__(16) unsigned char smem[];
    // layout: sA[2] at 0 / TILE_A ; sB[2] at 2*TILE_A + buf*TILE_B
    unsigned char* sA0 = smem;
    unsigned char* sB0 = smem + 2 * TILE_A;

    const int tid = threadIdx.x;
    const int n0  = blockIdx.x * NT;

    // B dequant mapping: thread -> (weight row 0..31, 16-int segment 0..7)
    const int brow = tid >> 3;              // 0..31
    const int bseg = tid & 7;               // 0..7
    const int4* qbase = reinterpret_cast<const int4*>(qw)
                      + (size_t)(n0 + brow) * (K_DIM / 4) + bseg * 4;
    const unsigned bSto = (unsigned)brow * BROW + (unsigned)bseg * 32;

    // A producer mapping: thread -> four 16B chunks of the 64x256B bf16 tile
    //   u = tid + j*256 (0..1023): row = u>>4, off = u&15
    const int4* xb = reinterpret_cast<const int4*>(g_x_bf16); // 512 int4 per row

    // MMA mapping: 8 warps as 4(M) x 2(N); warp tile 16m x 16n
    const int warp = tid >> 5, lane = tid & 31;
    const int wm = warp >> 1;               // 0..3
    const int wn = warp & 1;                // 0..1
    const int g4 = lane >> 2, tg = lane & 3;

    // ldmatrix per-lane base addresses (buf 0)
    const unsigned sAu = smem_u32(sA0);
    const unsigned sBu = smem_u32(sB0);
    const unsigned aFrag = sAu + (unsigned)(wm * 16 + (lane & 15)) * BROW
                               + (unsigned)((lane >> 4) & 1) * 16;
    const unsigned bFrag = sBu + (unsigned)(wn * 16 + ((lane >> 4) & 1) * 8 + (lane & 7)) * BROW
                               + (unsigned)((lane >> 3) & 1) * 16;

    float acc[2][4];
#pragma unroll
    for (int i = 0; i < 2; i++)
#pragma unroll
        for (int j = 0; j < 4; j++) acc[i][j] = 0.0f;

    int4 qr[4], qn[4];   // raw qweight (16 ints = this thread's slice)
    int  s2v, zv, s2n, zn;

    // prefetch group 0 weights
#pragma unroll
    for (int j = 0; j < 4; j++) qr[j] = qbase[j];
    s2v = s2s[n0 + brow];
    zv  = s2z[n0 + brow];

    for (int g = 0; g < G_DIM; ++g) {
        const int buf = g & 1;

        // ---- A tile: load 64B of bf16 x (L2-hot) and store to smem ----
        int4 xr[4];
#pragma unroll
        for (int j = 0; j < 4; j++) {
            const int u = tid + j * 256;
            xr[j] = xb[(u >> 4) * 512 + g * 16 + (u & 15)];
        }

        // ---- dequant 16 weights -> bf16, store 32B into sB ----
        unsigned pk[8];
#pragma unroll
        for (int j = 0; j < 4; j++) {
            float f0 = (float)(qr[j].x * s2v + zv);
            float f1 = (float)(qr[j].y * s2v + zv);
            float f2 = (float)(qr[j].z * s2v + zv);
            float f3 = (float)(qr[j].w * s2v + zv);
            pk[2*j]   = bf16x2(f1, f0);
            pk[2*j+1] = bf16x2(f3, f2);
        }
        {
            unsigned char* dst = sB0 + buf * TILE_B + bSto;
            *reinterpret_cast<uint4*>(dst)      = make_uint4(pk[0], pk[1], pk[2], pk[3]);
            *reinterpret_cast<uint4*>(dst + 16) = make_uint4(pk[4], pk[5], pk[6], pk[7]);
        }
#pragma unroll
        for (int j = 0; j < 4; j++) {
            const int u = tid + j * 256;
            *reinterpret_cast<int4*>(sA0 + buf * TILE_A + (u >> 4) * BROW + (u & 15) * 16) = xr[j];
        }

        // ---- prefetch next group's weights (covered by MMA phase) ----
        if (g + 1 < G_DIM) {
            const int4* qp = qbase + (g + 1) * (GS / 4);
#pragma unroll
            for (int j = 0; j < 4; j++) qn[j] = qp[j];
            s2n = s2s[(g + 1) * N_DIM + n0 + brow];
            zn  = s2z[(g + 1) * N_DIM + n0 + brow];
        }

        __syncthreads();   // tile (buf) complete; double buffer => 1 sync/iter

        // ---- MMA over this K=128 chunk: 8 k16-steps x 2 n8-subtiles ----
        const unsigned aOff = aFrag + (unsigned)buf * TILE_A;
        const unsigned bOff = bFrag + (unsigned)buf * TILE_B;
#pragma unroll
        for (int ks = 0; ks < 8; ks++) {
            unsigned a0, a1, a2, a3, b0, b1, b2, b3;
            asm volatile(
                "ldmatrix.sync.aligned.m8n8.x4.shared.b16 {%0,%1,%2,%3}, [%4];"
                : "=r"(a0), "=r"(a1), "=r"(a2), "=r"(a3)
                : "r"(aOff + ks * 32));
            asm volatile(
                "ldmatrix.sync.aligned.m8n8.x4.shared.b16 {%0,%1,%2,%3}, [%4];"
                : "=r"(b0), "=r"(b1), "=r"(b2), "=r"(b3)
                : "r"(bOff + ks * 32));
            asm volatile(
                "mma.sync.aligned.m16n8k16.row.col.f32.bf16.bf16.f32 "
                "{%0,%1,%2,%3}, {%4,%5,%6,%7}, {%8,%9}, {%0,%1,%2,%3};\n"
                : "+f"(acc[0][0]), "+f"(acc[0][1]), "+f"(acc[0][2]), "+f"(acc[0][3])
                : "r"(a0), "r"(a1), "r"(a2), "r"(a3), "r"(b0), "r"(b1));
            asm volatile(
                "mma.sync.aligned.m16n8k16.row.col.f32.bf16.bf16.f32 "
                "{%0,%1,%2,%3}, {%4,%5,%6,%7}, {%8,%9}, {%0,%1,%2,%3};\n"
                : "+f"(acc[1][0]), "+f"(acc[1][1]), "+f"(acc[1][2]), "+f"(acc[1][3])
                : "r"(a0), "r"(a1), "r"(a2), "r"(a3), "r"(b2), "r"(b3));
        }

        // rotate prefetch registers
#pragma unroll
        for (int j = 0; j < 4; j++) qr[j] = qn[j];
        s2v = s2n; zv = zn;
    }

    // ---- epilogue: out = acc * isc[m] * s1[n] + bias[n] ----
    const int m0 = wm * 16 + g4;
    const float isc0 = isc[m0];
    const float isc1 = isc[m0 + 8];
#pragma unroll
    for (int ns = 0; ns < 2; ns++) {
        const int n = n0 + wn * 16 + ns * 8 + tg * 2;
        const float s1a = s1[n],   s1b = s1[n + 1];
        const float ba  = bias[n], bb  = bias[n + 1];
        out[ m0      * N_DIM + n    ] = acc[ns][0] * isc0 * s1a + ba;
        out[ m0      * N_DIM + n + 1] = acc[ns][1] * isc0 * s1b + bb;
        out[(m0 + 8) * N_DIM + n    ] = acc[ns][2] * isc1 * s1a + ba;
        out[(m0 + 8) * N_DIM + n + 1] = acc[ns][3] * isc1 * s1b + bb;
    }
}

// ---------------------------------------------------------------------------
extern "C" void kernel_launch(void* const* d_in, const int* in_sizes, int n_in,
                              void* d_out, int out_size) {
    const int*   x    = (const int*)  d_in[0];  // [M,K] int32 (int8 values)
    const float* isc  = (const float*)d_in[1];  // [M]
    // d_in[2] = input_sum (unused)
    const int*   qw   = (const int*)  d_in[3];  // [N,K] int32 (uint4 values)
    const int*   s2s  = (const int*)  d_in[4];  // [G,N]
    const int*   s2z  = (const int*)  d_in[5];  // [G,N]
    const float* s1   = (const float*)d_in[6];  // [N]
    const float* bias = (const float*)d_in[7];  // [N]
    float* out = (float*)d_out;

    cudaFuncSetAttribute(w4a8_gemm_kernel,
                         cudaFuncAttributeMaxDynamicSharedMemorySize, SMEM_TOTAL);

    pack_x_kernel<<<(M_DIM * K_DIM / 4 + 255) / 256, 256>>>(x);
    w4a8_gemm_kernel<<<N_DIM / NT, THREADS, SMEM_TOTAL>>>(qw, s2s, s2z, isc, s1, bias, out);
}

// round 10
// speedup vs baseline: 1.0162x; 1.0162x over previous
#include <cuda_runtime.h>
#include <stdint.h>

// ---------------------------------------------------------------------------
// W4A8 per-group GEMM via legacy bf16 HMMA (tensor busy only ~12us vs IMMA's
// 47.8us wall). Round 10 attacks the L1/smem-bandwidth binder (87% in R9):
//  - warps split K (4 wm x 2 kh), not N: fragment LDS 64->48KB/CTA-group
//  - A pre-fragmented in gmem (pack kernel emits mma register order): no A
//    smem tile at all; 4 coalesced LDG.128/warp/group from an L2-hot 512KB
//    buffer shared by ALL CTAs
//  - qweight streamed with cp.async.cg into raw smem (own-data layout,
//    validated R4): frees 32 staging registers -> 3 CTAs/SM
// Exactness: x in [-128,127], w = q*s2+z in [-105,105] exact in bf16;
// fp32 accumulation == fp32 reference einsum.
// ---------------------------------------------------------------------------

#define M_DIM 64
#define K_DIM 4096
#define N_DIM 14336
#define G_DIM 32
#define NT    32             // output channels per CTA -> 448 CTAs
#define BROW  272            // bf16 B-tile row bytes (256 data + 16 pad)
#define THREADS 256
#define TILE_B (NT * BROW)           // 8704
#define RAW_BYTES 16384              // 32 rows x 128 ints x 4B
#define OFF_RAW(b)  ((b) * RAW_BYTES)
#define OFF_B(b)    (2 * RAW_BYTES + (b) * TILE_B)
#define SMEM_TOTAL  (2 * RAW_BYTES + 2 * TILE_B)   // 50176

#define CP_ASYNC16(dst, src) \
    asm volatile("cp.async.cg.shared.global [%0], [%1], 16;" :: "r"(dst), "l"(src))
#define CP_COMMIT()  asm volatile("cp.async.commit_group;")
#define CP_WAIT(N)   asm volatile("cp.async.wait_group %0;" :: "n"(N))

__device__ __forceinline__ unsigned smem_u32(const void* p) {
    unsigned a;
    asm("{ .reg .u64 t; cvta.to.shared.u64 t, %1; cvt.u32.u64 %0, t; }" : "=r"(a) : "l"(p));
    return a;
}
// pack two fp32 -> bf16x2 word: hi = fhi, lo = flo
__device__ __forceinline__ unsigned bf16x2(float fhi, float flo) {
    unsigned r;
    asm("cvt.rn.bf16x2.f32 %0, %1, %2;" : "=r"(r) : "f"(fhi), "f"(flo));
    return r;
}

// A fragments, mma.m16n8k16 register order:
// uint4 index = g*1024 + wm*256 + kh*128 + ks*32 + lane  (512 KB total)
__device__ __align__(16) uint4 g_x_frag[G_DIM * 4 * 2 * 4 * 32];

// ---- pass 0: pack x int32 -> bf16 A-fragments --------------------------------
__global__ void pack_x_frag_kernel(const int* __restrict__ x) {
    const int t = blockIdx.x * blockDim.x + threadIdx.x;
    if (t >= G_DIM * 1024) return;
    const int lane = t & 31;
    const int ks   = (t >> 5) & 3;
    const int kh   = (t >> 7) & 1;
    const int wm   = (t >> 8) & 3;
    const int g    = t >> 10;
    const int g4 = lane >> 2, tg = lane & 3;
    const int r0 = wm * 16 + g4, r1 = r0 + 8;
    const int kb = g * 128 + kh * 64 + ks * 16 + tg * 2;
    const int* x0 = x + r0 * K_DIM + kb;
    const int* x1 = x + r1 * K_DIM + kb;
    uint4 v;
    v.x = bf16x2((float)x0[1], (float)x0[0]);   // a0: row-lo, k-lo
    v.y = bf16x2((float)x1[1], (float)x1[0]);   // a1: row-hi, k-lo
    v.z = bf16x2((float)x0[9], (float)x0[8]);   // a2: row-lo, k-hi
    v.w = bf16x2((float)x1[9], (float)x1[8]);   // a3: row-hi, k-hi
    g_x_frag[t] = v;
}

// ---- main GEMM ---------------------------------------------------------------
__global__ __launch_bounds__(THREADS, 3)
void w4a8_gemm_kernel(const int*   __restrict__ qw,    // [N,K] int32 (0..15)
                      const int*   __restrict__ s2s,   // [G,N]
                      const int*   __restrict__ s2z,   // [G,N]
                      const float* __restrict__ isc,   // [M]
                      const float* __restrict__ s1,    // [N]
                      const float* __restrict__ bias,  // [N]
                      float*       __restrict__ out)   // [M,N]
{
    extern __shared__ __align__(16) unsigned char smem[];
    const unsigned sbase = smem_u32(smem);

    const int tid = threadIdx.x;
    const int n0  = blockIdx.x * NT;

    // qweight producer mapping: thread -> (row 0..31, 64B slice 0..7)
    const int brow = tid >> 3;
    const int bseg = tid & 7;
    const char* gsrc = reinterpret_cast<const char*>(qw + (size_t)(n0 + brow) * K_DIM)
                     + bseg * 64;
    // raw smem: own-data chunks, conflict-free LDS.128 readback
    const unsigned roff0 = (unsigned)(tid >> 3) * 512u + (unsigned)(tid & 7) * 16u;

    // warp org: 4 wm (m16 rows) x 2 kh (k-halves of each group)
    const int warp = tid >> 5, lane = tid & 31;
    const int wm = warp >> 1;
    const int kh = warp & 1;
    const int g4 = lane >> 2, tg = lane & 3;

    // A-fragment gmem pointer (uint4 units)
    const uint4* aptr = g_x_frag + wm * 256 + kh * 128 + lane;

    // B ldmatrix base (buf 0): rows (0-7|8-15) + 16*BROW for rows 16-31
    const unsigned bAddr0 = sbase + OFF_B(0)
        + (unsigned)(((lane >> 4) & 1) * 8 + (lane & 7)) * BROW
        + (unsigned)kh * 128u + (unsigned)((lane >> 3) & 1) * 16u;

    float acc[4][4];
#pragma unroll
    for (int i = 0; i < 4; i++)
#pragma unroll
        for (int j = 0; j < 4; j++) acc[i][j] = 0.0f;

    // ---- prologue: stream raw qweight groups 0 and 1 ----
#pragma unroll
    for (int s = 0; s < 2; s++) {
        const unsigned dst = sbase + OFF_RAW(s) + roff0;
        const char* src = gsrc + (size_t)s * 512;
#pragma unroll
        for (int j = 0; j < 4; j++) CP_ASYNC16(dst + j * 128u, src + j * 16);
        CP_COMMIT();
    }
    int s2v = s2s[n0 + brow];
    int zv  = s2z[n0 + brow];

    for (int g = 0; g < G_DIM; ++g) {
        const int buf = g & 1;

        // ---- A fragments for this group (L1/L2-hot, 4 coalesced LDG.128) ----
        const uint4* ap = aptr + g * 1024;
        uint4 ar0 = ap[0], ar1 = ap[32], ar2 = ap[64], ar3 = ap[96];

        // ---- wait for raw(g), dequant -> bf16, STS into sB[buf] ----
        if (g == G_DIM - 1) { CP_WAIT(0); } else { CP_WAIT(1); }
        unsigned pk[8];
        const unsigned rbase = sbase + OFF_RAW(buf) + roff0;
#pragma unroll
        for (int j = 0; j < 4; j++) {
            int4 q = *reinterpret_cast<const int4*>(smem + (rbase - sbase) + j * 128u);
            float f0 = (float)(q.x * s2v + zv);
            float f1 = (float)(q.y * s2v + zv);
            float f2 = (float)(q.z * s2v + zv);
            float f3 = (float)(q.w * s2v + zv);
            pk[2 * j]     = bf16x2(f1, f0);
            pk[2 * j + 1] = bf16x2(f3, f2);
        }
        {
            unsigned char* dst = smem + OFF_B(buf) + brow * BROW + bseg * 32;
            *reinterpret_cast<uint4*>(dst)      = make_uint4(pk[0], pk[1], pk[2], pk[3]);
            *reinterpret_cast<uint4*>(dst + 16) = make_uint4(pk[4], pk[5], pk[6], pk[7]);
        }

        // ---- stream raw(g+2) into the buffer just consumed ----
        if (g + 2 < G_DIM) {
            const char* src = gsrc + (size_t)(g + 2) * 512;
#pragma unroll
            for (int j = 0; j < 4; j++) CP_ASYNC16(rbase + j * 128u, src + j * 16);
            CP_COMMIT();
        }

        // ---- scales for next group ----
        int s2n = 0, zn = 0;
        if (g + 1 < G_DIM) {
            s2n = s2s[(g + 1) * N_DIM + n0 + brow];
            zn  = s2z[(g + 1) * N_DIM + n0 + brow];
        }

        __syncthreads();   // sB[buf] complete; double buffer => 1 sync/iter

        // ---- MMA: this warp's k-half (4 k16-steps) x full n32 ----
        const unsigned bA = bAddr0 + (unsigned)buf * TILE_B;
#pragma unroll
        for (int ks = 0; ks < 4; ks++) {
            const uint4 a = (ks == 0) ? ar0 : (ks == 1) ? ar1 : (ks == 2) ? ar2 : ar3;
            unsigned b0, b1, b2, b3, b4, b5, b6, b7;
            asm volatile(
                "ldmatrix.sync.aligned.m8n8.x4.shared.b16 {%0,%1,%2,%3}, [%4];"
                : "=r"(b0), "=r"(b1), "=r"(b2), "=r"(b3)
                : "r"(bA + ks * 32));
            asm volatile(
                "ldmatrix.sync.aligned.m8n8.x4.shared.b16 {%0,%1,%2,%3}, [%4];"
                : "=r"(b4), "=r"(b5), "=r"(b6), "=r"(b7)
                : "r"(bA + 16 * BROW + ks * 32));
            asm volatile(
                "mma.sync.aligned.m16n8k16.row.col.f32.bf16.bf16.f32 "
                "{%0,%1,%2,%3}, {%4,%5,%6,%7}, {%8,%9}, {%0,%1,%2,%3};\n"
                : "+f"(acc[0][0]), "+f"(acc[0][1]), "+f"(acc[0][2]), "+f"(acc[0][3])
                : "r"(a.x), "r"(a.y), "r"(a.z), "r"(a.w), "r"(b0), "r"(b1));
            asm volatile(
                "mma.sync.aligned.m16n8k16.row.col.f32.bf16.bf16.f32 "
                "{%0,%1,%2,%3}, {%4,%5,%6,%7}, {%8,%9}, {%0,%1,%2,%3};\n"
                : "+f"(acc[1][0]), "+f"(acc[1][1]), "+f"(acc[1][2]), "+f"(acc[1][3])
                : "r"(a.x), "r"(a.y), "r"(a.z), "r"(a.w), "r"(b2), "r"(b3));
            asm volatile(
                "mma.sync.aligned.m16n8k16.row.col.f32.bf16.bf16.f32 "
                "{%0,%1,%2,%3}, {%4,%5,%6,%7}, {%8,%9}, {%0,%1,%2,%3};\n"
                : "+f"(acc[2][0]), "+f"(acc[2][1]), "+f"(acc[2][2]), "+f"(acc[2][3])
                : "r"(a.x), "r"(a.y), "r"(a.z), "r"(a.w), "r"(b4), "r"(b5));
            asm volatile(
                "mma.sync.aligned.m16n8k16.row.col.f32.bf16.bf16.f32 "
                "{%0,%1,%2,%3}, {%4,%5,%6,%7}, {%8,%9}, {%0,%1,%2,%3};\n"
                : "+f"(acc[3][0]), "+f"(acc[3][1]), "+f"(acc[3][2]), "+f"(acc[3][3])
                : "r"(a.x), "r"(a.y), "r"(a.z), "r"(a.w), "r"(b6), "r"(b7));
        }

        s2v = s2n; zv = zn;
    }

    // ---- k-half reduction via smem (raw buffers are dead now) ----
    __syncthreads();
    float* sRed = reinterpret_cast<float*>(smem);   // [64][32] f32 = 8KB
    const int rbase0 = (wm * 16 + g4) * 32 + tg * 2;
    if (kh == 1) {
#pragma unroll
        for (int ns = 0; ns < 4; ns++) {
            sRed[rbase0 + ns * 8]           = acc[ns][0];
            sRed[rbase0 + ns * 8 + 1]       = acc[ns][1];
            sRed[rbase0 + 256 + ns * 8]     = acc[ns][2];   // row +8
            sRed[rbase0 + 256 + ns * 8 + 1] = acc[ns][3];
        }
    }
    __syncthreads();
    if (kh == 0) {
        const int m0 = wm * 16 + g4;
        const float isc0 = isc[m0];
        const float isc1 = isc[m0 + 8];
#pragma unroll
        for (int ns = 0; ns < 4; ns++) {
            const int n = n0 + ns * 8 + tg * 2;
            const float s1a = s1[n],   s1b = s1[n + 1];
            const float ba  = bias[n], bb  = bias[n + 1];
            const float v0 = acc[ns][0] + sRed[rbase0 + ns * 8];
            const float v1 = acc[ns][1] + sRed[rbase0 + ns * 8 + 1];
            const float v2 = acc[ns][2] + sRed[rbase0 + 256 + ns * 8];
            const float v3 = acc[ns][3] + sRed[rbase0 + 256 + ns * 8 + 1];
            out[ m0      * N_DIM + n    ] = v0 * isc0 * s1a + ba;
            out[ m0      * N_DIM + n + 1] = v1 * isc0 * s1b + bb;
            out[(m0 + 8) * N_DIM + n    ] = v2 * isc1 * s1a + ba;
            out[(m0 + 8) * N_DIM + n + 1] = v3 * isc1 * s1b + bb;
        }
    }
}

// ---------------------------------------------------------------------------
extern "C" void kernel_launch(void* const* d_in, const int* in_sizes, int n_in,
                              void* d_out, int out_size) {
    const int*   x    = (const int*)  d_in[0];  // [M,K] int32 (int8 values)
    const float* isc  = (const float*)d_in[1];  // [M]
    // d_in[2] = input_sum (unused)
    const int*   qw   = (const int*)  d_in[3];  // [N,K] int32 (uint4 values)
    const int*   s2s  = (const int*)  d_in[4];  // [G,N]
    const int*   s2z  = (const int*)  d_in[5];  // [G,N]
    const float* s1   = (const float*)d_in[6];  // [N]
    const float* bias = (const float*)d_in[7];  // [N]
    float* out = (float*)d_out;

    cudaFuncSetAttribute(w4a8_gemm_kernel,
                         cudaFuncAttributeMaxDynamicSharedMemorySize, SMEM_TOTAL);

    pack_x_frag_kernel<<<G_DIM * 1024 / 256, 256>>>(x);
    w4a8_gemm_kernel<<<N_DIM / NT, THREADS, SMEM_TOTAL>>>(qw, s2s, s2z, isc, s1, bias, out);
}

// round 11
// speedup vs baseline: 1.0675x; 1.0504x over previous
#include <cuda_runtime.h>
#include <stdint.h>

// ---------------------------------------------------------------------------
// W4A8 per-group GEMM via legacy bf16 HMMA (bf16 tensor busy ~12us vs legacy
// IMMA's hard 47.8us wall). R10 was barrier-bound (issue 15.7%, occ at its
// 37.8% structural cap, nothing saturated). Round 11: HALVE the barrier count
// — 2 groups per __syncthreads with 4 B-tile buffers; raw qweight in 2x16KB
// cp.async buffers (even/odd group). Everything else = R10:
//  - A pre-fragmented in gmem in mma register order (no A smem tile)
//  - warps split K (4 wm x 2 kh), k-half reduction in smem at epilogue
// Exactness: x in [-128,127], w=q*s2+z in [-105,105] exact in bf16; fp32 acc.
// ---------------------------------------------------------------------------

#define M_DIM 64
#define K_DIM 4096
#define N_DIM 14336
#define G_DIM 32
#define NT    32             // output channels per CTA -> 448 CTAs
#define BROW  272            // bf16 B-tile row bytes (256 data + 16 pad)
#define THREADS 256
#define TILE_B (NT * BROW)           // 8704
#define RAW_BYTES 16384              // one group: 32 rows x 128 ints x 4B
#define OFF_RAW(b)  ((b) * RAW_BYTES)
#define OFF_B(i)    (2 * RAW_BYTES + (i) * TILE_B)
#define SMEM_TOTAL  (2 * RAW_BYTES + 4 * TILE_B)   // 67584

#define CP_ASYNC16(dst, src) \
    asm volatile("cp.async.cg.shared.global [%0], [%1], 16;" :: "r"(dst), "l"(src))
#define CP_COMMIT()  asm volatile("cp.async.commit_group;")
#define CP_WAIT(N)   asm volatile("cp.async.wait_group %0;" :: "n"(N))

__device__ __forceinline__ unsigned smem_u32(const void* p) {
    unsigned a;
    asm("{ .reg .u64 t; cvta.to.shared.u64 t, %1; cvt.u32.u64 %0, t; }" : "=r"(a) : "l"(p));
    return a;
}
// pack two fp32 -> bf16x2 word: hi = fhi, lo = flo
__device__ __forceinline__ unsigned bf16x2(float fhi, float flo) {
    unsigned r;
    asm("cvt.rn.bf16x2.f32 %0, %1, %2;" : "=r"(r) : "f"(fhi), "f"(flo));
    return r;
}

// A fragments, mma.m16n8k16 register order:
// uint4 index = g*1024 + wm*256 + kh*128 + ks*32 + lane  (512 KB total)
__device__ __align__(16) uint4 g_x_frag[G_DIM * 4 * 2 * 4 * 32];

// ---- pass 0: pack x int32 -> bf16 A-fragments --------------------------------
__global__ void pack_x_frag_kernel(const int* __restrict__ x) {
    const int t = blockIdx.x * blockDim.x + threadIdx.x;
    if (t >= G_DIM * 1024) return;
    const int lane = t & 31;
    const int ks   = (t >> 5) & 3;
    const int kh   = (t >> 7) & 1;
    const int wm   = (t >> 8) & 3;
    const int g    = t >> 10;
    const int g4 = lane >> 2, tg = lane & 3;
    const int r0 = wm * 16 + g4, r1 = r0 + 8;
    const int kb = g * 128 + kh * 64 + ks * 16 + tg * 2;
    const int* x0 = x + r0 * K_DIM + kb;
    const int* x1 = x + r1 * K_DIM + kb;
    uint4 v;
    v.x = bf16x2((float)x0[1], (float)x0[0]);   // a0: row-lo, k-lo
    v.y = bf16x2((float)x1[1], (float)x1[0]);   // a1: row-hi, k-lo
    v.z = bf16x2((float)x0[9], (float)x0[8]);   // a2: row-lo, k-hi
    v.w = bf16x2((float)x1[9], (float)x1[8]);   // a3: row-hi, k-hi
    g_x_frag[t] = v;
}

// 4 HMMAs of one k16-step against a 4-fragment B column set
#define MMA_STEP(ACC, A, B0, B1, B2, B3, B4, B5, B6, B7)                          \
    do {                                                                          \
        asm volatile(                                                             \
            "mma.sync.aligned.m16n8k16.row.col.f32.bf16.bf16.f32 "                \
            "{%0,%1,%2,%3}, {%4,%5,%6,%7}, {%8,%9}, {%0,%1,%2,%3};\n"             \
            : "+f"(ACC[0][0]), "+f"(ACC[0][1]), "+f"(ACC[0][2]), "+f"(ACC[0][3])  \
            : "r"((A).x), "r"((A).y), "r"((A).z), "r"((A).w), "r"(B0), "r"(B1));  \
        asm volatile(                                                             \
            "mma.sync.aligned.m16n8k16.row.col.f32.bf16.bf16.f32 "                \
            "{%0,%1,%2,%3}, {%4,%5,%6,%7}, {%8,%9}, {%0,%1,%2,%3};\n"             \
            : "+f"(ACC[1][0]), "+f"(ACC[1][1]), "+f"(ACC[1][2]), "+f"(ACC[1][3])  \
            : "r"((A).x), "r"((A).y), "r"((A).z), "r"((A).w), "r"(B2), "r"(B3));  \
        asm volatile(                                                             \
            "mma.sync.aligned.m16n8k16.row.col.f32.bf16.bf16.f32 "                \
            "{%0,%1,%2,%3}, {%4,%5,%6,%7}, {%8,%9}, {%0,%1,%2,%3};\n"             \
            : "+f"(ACC[2][0]), "+f"(ACC[2][1]), "+f"(ACC[2][2]), "+f"(ACC[2][3])  \
            : "r"((A).x), "r"((A).y), "r"((A).z), "r"((A).w), "r"(B4), "r"(B5));  \
        asm volatile(                                                             \
            "mma.sync.aligned.m16n8k16.row.col.f32.bf16.bf16.f32 "                \
            "{%0,%1,%2,%3}, {%4,%5,%6,%7}, {%8,%9}, {%0,%1,%2,%3};\n"             \
            : "+f"(ACC[3][0]), "+f"(ACC[3][1]), "+f"(ACC[3][2]), "+f"(ACC[3][3])  \
            : "r"((A).x), "r"((A).y), "r"((A).z), "r"((A).w), "r"(B6), "r"(B7));  \
    } while (0)

// one group's MMA: 4 k16-steps x n32 from B tile at bA
#define MMA_GROUP(ACC, AR, bA)                                                    \
    do {                                                                          \
        _Pragma("unroll")                                                         \
        for (int ks = 0; ks < 4; ks++) {                                          \
            const uint4 a = (ks == 0) ? AR##0 : (ks == 1) ? AR##1                 \
                          : (ks == 2) ? AR##2 : AR##3;                            \
            unsigned b0, b1, b2, b3, b4, b5, b6, b7;                              \
            asm volatile(                                                         \
                "ldmatrix.sync.aligned.m8n8.x4.shared.b16 {%0,%1,%2,%3}, [%4];"   \
                : "=r"(b0), "=r"(b1), "=r"(b2), "=r"(b3)                          \
                : "r"((bA) + ks * 32));                                           \
            asm volatile(                                                         \
                "ldmatrix.sync.aligned.m8n8.x4.shared.b16 {%0,%1,%2,%3}, [%4];"   \
                : "=r"(b4), "=r"(b5), "=r"(b6), "=r"(b7)                          \
                : "r"((bA) + 16 * BROW + ks * 32));                               \
            MMA_STEP(ACC, a, b0, b1, b2, b3, b4, b5, b6, b7);                     \
        }                                                                         \
    } while (0)

// dequant one raw buffer (own 16 ints) -> 32B bf16 STS
#define DEQUANT_STORE(RBUF, S2, ZZ, BDST)                                         \
    do {                                                                          \
        unsigned pk[8];                                                           \
        _Pragma("unroll")                                                         \
        for (int j = 0; j < 4; j++) {                                             \
            int4 q = *reinterpret_cast<const int4*>(                              \
                smem + OFF_RAW(RBUF) + roffc + j * 128u);                         \
            float f0 = (float)(q.x * (S2) + (ZZ));                                \
            float f1 = (float)(q.y * (S2) + (ZZ));                                \
            float f2 = (float)(q.z * (S2) + (ZZ));                                \
            float f3 = (float)(q.w * (S2) + (ZZ));                                \
            pk[2 * j]     = bf16x2(f1, f0);                                       \
            pk[2 * j + 1] = bf16x2(f3, f2);                                       \
        }                                                                         \
        unsigned char* dst = smem + (BDST);                                       \
        *reinterpret_cast<uint4*>(dst)      = make_uint4(pk[0], pk[1], pk[2], pk[3]); \
        *reinterpret_cast<uint4*>(dst + 16) = make_uint4(pk[4], pk[5], pk[6], pk[7]); \
    } while (0)

// ---- main GEMM ---------------------------------------------------------------
__global__ __launch_bounds__(THREADS, 3)
void w4a8_gemm_kernel(const int*   __restrict__ qw,    // [N,K] int32 (0..15)
                      const int*   __restrict__ s2s,   // [G,N]
                      const int*   __restrict__ s2z,   // [G,N]
                      const float* __restrict__ isc,   // [M]
                      const float* __restrict__ s1,    // [N]
                      const float* __restrict__ bias,  // [N]
                      float*       __restrict__ out)   // [M,N]
{
    extern __shared__ __align__(16) unsigned char smem[];
    const unsigned sbase = smem_u32(smem);

    const int tid = threadIdx.x;
    const int n0  = blockIdx.x * NT;

    // qweight producer mapping: thread -> (row 0..31, 64B slice 0..7 of a group)
    const int brow = tid >> 3;
    const int bseg = tid & 7;
    const char* gsrc = reinterpret_cast<const char*>(qw + (size_t)(n0 + brow) * K_DIM)
                     + bseg * 64;
    // raw smem: own-data chunks (j*128B spread), conflict-free LDS.128 readback
    const unsigned roffc = (unsigned)brow * 512u + (unsigned)bseg * 16u;
    const unsigned bSto  = (unsigned)brow * BROW + (unsigned)bseg * 32u;

    // warp org: 4 wm (m16 rows) x 2 kh (k-halves of each group)
    const int warp = tid >> 5, lane = tid & 31;
    const int wm = warp >> 1;
    const int kh = warp & 1;
    const int g4 = lane >> 2, tg = lane & 3;

    // A-fragment gmem pointer (uint4 units)
    const uint4* aptr = g_x_frag + wm * 256 + kh * 128 + lane;

    // B ldmatrix base (buffer 0)
    const unsigned bAddr0 = sbase + OFF_B(0)
        + (unsigned)(((lane >> 4) & 1) * 8 + (lane & 7)) * BROW
        + (unsigned)kh * 128u + (unsigned)((lane >> 3) & 1) * 16u;

    float acc[4][4];
#pragma unroll
    for (int i = 0; i < 4; i++)
#pragma unroll
        for (int j = 0; j < 4; j++) acc[i][j] = 0.0f;

    // ---- prologue: stream raw groups 0 (raw0) and 1 (raw1) ----
#pragma unroll
    for (int s = 0; s < 2; s++) {
        const unsigned dst = sbase + OFF_RAW(s) + roffc;
        const char* src = gsrc + (size_t)s * 512;
#pragma unroll
        for (int j = 0; j < 4; j++) CP_ASYNC16(dst + j * 128u, src + j * 16);
        CP_COMMIT();
    }
    int s2a = s2s[n0 + brow],         za = s2z[n0 + brow];
    int s2b = s2s[N_DIM + n0 + brow], zb = s2z[N_DIM + n0 + brow];

    for (int p = 0; p < G_DIM / 2; ++p) {
        const int a  = 2 * p;
        const int ba = 2 * (p & 1);     // B buffer pair {ba, ba+1}

        // A fragments for group a (L1/L2-hot coalesced LDG.128)
        const uint4* apa = aptr + a * 1024;
        uint4 ar0 = apa[0], ar1 = apa[32], ar2 = apa[64], ar3 = apa[96];

        // ---- consume raw0 (group a): dequant -> sB[ba], refill with a+2 ----
        CP_WAIT(1);
        DEQUANT_STORE(0, s2a, za, OFF_B(ba) + bSto);
        if (a + 2 < G_DIM) {
            const unsigned dst = sbase + OFF_RAW(0) + roffc;
            const char* src = gsrc + (size_t)(a + 2) * 512;
#pragma unroll
            for (int j = 0; j < 4; j++) CP_ASYNC16(dst + j * 128u, src + j * 16);
            CP_COMMIT();
        }

        // ---- consume raw1 (group a+1): dequant -> sB[ba+1], refill a+3 ----
        if (p == G_DIM / 2 - 1) { CP_WAIT(0); } else { CP_WAIT(1); }
        DEQUANT_STORE(1, s2b, zb, OFF_B(ba + 1) + bSto);
        if (a + 3 < G_DIM) {
            const unsigned dst = sbase + OFF_RAW(1) + roffc;
            const char* src = gsrc + (size_t)(a + 3) * 512;
#pragma unroll
            for (int j = 0; j < 4; j++) CP_ASYNC16(dst + j * 128u, src + j * 16);
            CP_COMMIT();
        }

        // ---- prefetch next pair's scales ----
        if (p + 1 < G_DIM / 2) {
            s2a = s2s[(a + 2) * N_DIM + n0 + brow];
            za  = s2z[(a + 2) * N_DIM + n0 + brow];
            s2b = s2s[(a + 3) * N_DIM + n0 + brow];
            zb  = s2z[(a + 3) * N_DIM + n0 + brow];
        }

        __syncthreads();   // ONE barrier per 2 groups

        // ---- MMA group a, then group a+1 ----
        {
            const uint4* apb = aptr + (a + 1) * 1024;
            uint4 br0 = apb[0], br1 = apb[32], br2 = apb[64], br3 = apb[96];
            MMA_GROUP(acc, ar, bAddr0 + (unsigned)ba * TILE_B);
            MMA_GROUP(acc, br, bAddr0 + (unsigned)(ba + 1) * TILE_B);
        }
    }

    // ---- k-half reduction via smem (raw buffers are dead now) ----
    __syncthreads();
    float* sRed = reinterpret_cast<float*>(smem);   // [64][32] f32 = 8KB
    const int rbase0 = (wm * 16 + g4) * 32 + tg * 2;
    if (kh == 1) {
#pragma unroll
        for (int ns = 0; ns < 4; ns++) {
            sRed[rbase0 + ns * 8]           = acc[ns][0];
            sRed[rbase0 + ns * 8 + 1]       = acc[ns][1];
            sRed[rbase0 + 256 + ns * 8]     = acc[ns][2];   // row +8
            sRed[rbase0 + 256 + ns * 8 + 1] = acc[ns][3];
        }
    }
    __syncthreads();
    if (kh == 0) {
        const int m0 = wm * 16 + g4;
        const float isc0 = isc[m0];
        const float isc1 = isc[m0 + 8];
#pragma unroll
        for (int ns = 0; ns < 4; ns++) {
            const int n = n0 + ns * 8 + tg * 2;
            const float s1a = s1[n],   s1b = s1[n + 1];
            const float ba2 = bias[n], bb2 = bias[n + 1];
            const float v0 = acc[ns][0] + sRed[rbase0 + ns * 8];
            const float v1 = acc[ns][1] + sRed[rbase0 + ns * 8 + 1];
            const float v2 = acc[ns][2] + sRed[rbase0 + 256 + ns * 8];
            const float v3 = acc[ns][3] + sRed[rbase0 + 256 + ns * 8 + 1];
            out[ m0      * N_DIM + n    ] = v0 * isc0 * s1a + ba2;
            out[ m0      * N_DIM + n + 1] = v1 * isc0 * s1b + bb2;
            out[(m0 + 8) * N_DIM + n    ] = v2 * isc1 * s1a + ba2;
            out[(m0 + 8) * N_DIM + n + 1] = v3 * isc1 * s1b + bb2;
        }
    }
}

// ---------------------------------------------------------------------------
extern "C" void kernel_launch(void* const* d_in, const int* in_sizes, int n_in,
                              void* d_out, int out_size) {
    const int*   x    = (const int*)  d_in[0];  // [M,K] int32 (int8 values)
    const float* isc  = (const float*)d_in[1];  // [M]
    // d_in[2] = input_sum (unused)
    const int*   qw   = (const int*)  d_in[3];  // [N,K] int32 (uint4 values)
    const int*   s2s  = (const int*)  d_in[4];  // [G,N]
    const int*   s2z  = (const int*)  d_in[5];  // [G,N]
    const float* s1   = (const float*)d_in[6];  // [N]
    const float* bias = (const float*)d_in[7];  // [N]
    float* out = (float*)d_out;

    cudaFuncSetAttribute(w4a8_gemm_kernel,
                         cudaFuncAttributeMaxDynamicSharedMemorySize, SMEM_TOTAL);

    pack_x_frag_kernel<<<G_DIM * 1024 / 256, 256>>>(x);
    w4a8_gemm_kernel<<<N_DIM / NT, THREADS, SMEM_TOTAL>>>(qw, s2s, s2z, isc, s1, bias, out);
}